// round 15
// baseline (speedup 1.0000x reference)
#include <cuda_runtime.h>
#include <cuda_bf16.h>
#include <cuda_fp16.h>
#include <math.h>
#include <stdint.h>

#define Bn 512
#define Vn 128
#define Dn 256
#define Hn 4
#define DHn 64

// ---------------- scratch (no cudaMalloc allowed) ----------------
__device__ __nv_bfloat16 g_Wh[Dn * Dn];         // W hi (bf16, gemm internal)
__device__ __nv_bfloat16 g_Wl[Dn * Dn];         // W lo
__device__ __half g_Wxh[(size_t)Bn * Vn * Dn];  // Wx hi (fp16)
__device__ __half g_Wxl[(size_t)Bn * Vn * Dn];  // Wx lo (fp16)
__device__ float g_sS[Hn * Bn * Vn];            // [h][b*V+i] s_src (fp32, from gemm)
__device__ float g_sD[Hn * Bn * Vn];            // [h][b*V+i] s_dst
__device__ float g_efm[Hn * Vn * Vn];           // TRANSPOSED: [h][j][i] = adj? ef : -1e30
__device__ unsigned int g_efgmax_u[Hn];         // encoded per-head global max
__device__ int   g_mask_mode;                   // 0=u8, 1=i32, 2=f32

#define NEGBIG (-1e30f)

// ---------------- helpers ----------------
__device__ __forceinline__ void mma_bf16(float* c, const uint32_t* a, uint32_t b0, uint32_t b1) {
    asm volatile(
        "mma.sync.aligned.m16n8k16.row.col.f32.bf16.bf16.f32 "
        "{%0,%1,%2,%3},{%4,%5,%6,%7},{%8,%9},{%0,%1,%2,%3};"
        : "+f"(c[0]), "+f"(c[1]), "+f"(c[2]), "+f"(c[3])
        : "r"(a[0]), "r"(a[1]), "r"(a[2]), "r"(a[3]), "r"(b0), "r"(b1));
}
__device__ __forceinline__ void mma_f16(float* c, const uint32_t* a, uint32_t b0, uint32_t b1) {
    asm volatile(
        "mma.sync.aligned.m16n8k16.row.col.f32.f16.f16.f32 "
        "{%0,%1,%2,%3},{%4,%5,%6,%7},{%8,%9},{%0,%1,%2,%3};"
        : "+f"(c[0]), "+f"(c[1]), "+f"(c[2]), "+f"(c[3])
        : "r"(a[0]), "r"(a[1]), "r"(a[2]), "r"(a[3]), "r"(b0), "r"(b1));
}

__device__ __forceinline__ void ldsm_x4(uint32_t& r0, uint32_t& r1, uint32_t& r2, uint32_t& r3,
                                        uint32_t addr) {
    asm volatile("ldmatrix.sync.aligned.m8n8.x4.shared.b16 {%0,%1,%2,%3}, [%4];"
                 : "=r"(r0), "=r"(r1), "=r"(r2), "=r"(r3) : "r"(addr));
}
__device__ __forceinline__ void ldsm_x4_t(uint32_t& r0, uint32_t& r1, uint32_t& r2, uint32_t& r3,
                                          uint32_t addr) {
    asm volatile("ldmatrix.sync.aligned.m8n8.x4.trans.shared.b16 {%0,%1,%2,%3}, [%4];"
                 : "=r"(r0), "=r"(r1), "=r"(r2), "=r"(r3) : "r"(addr));
}
__device__ __forceinline__ uint32_t sptr(const void* p) {
    return (uint32_t)__cvta_generic_to_shared(p);
}

#define CP_ASYNC16(dst, src) \
    asm volatile("cp.async.cg.shared.global [%0], [%1], 16;" ::"r"(dst), "l"(src))
#define CP_COMMIT() asm volatile("cp.async.commit_group;" ::: "memory")
#define CP_WAIT0()  asm volatile("cp.async.wait_group 0;" ::: "memory")

// bf16 hi/lo split (gemm internal)
__device__ __forceinline__ void split2(float a, float b, uint32_t& hi, uint32_t& lo) {
    __nv_bfloat16 ha = __float2bfloat16_rn(a);
    __nv_bfloat16 hb = __float2bfloat16_rn(b);
    float ra = a - __bfloat162float(ha);
    float rb = b - __bfloat162float(hb);
    __nv_bfloat162 vh; vh.x = ha; vh.y = hb;
    __nv_bfloat162 vl; vl.x = __float2bfloat16_rn(ra); vl.y = __float2bfloat16_rn(rb);
    hi = *reinterpret_cast<uint32_t*>(&vh);
    lo = *reinterpret_cast<uint32_t*>(&vl);
}

// fp16 hi/lo split (Wx storage)
__device__ __forceinline__ void split2h(float a, float b, uint32_t& hi, uint32_t& lo) {
    __half2 vh = __floats2half2_rn(a, b);
    float ra = a - __half2float(vh.x);
    float rb = b - __half2float(vh.y);
    __half2 vl = __floats2half2_rn(ra, rb);
    hi = *reinterpret_cast<uint32_t*>(&vh);
    lo = *reinterpret_cast<uint32_t*>(&vl);
}

__device__ __forceinline__ float lrelu(float s) { return (s >= 0.f) ? s : 0.2f * s; }

__device__ __forceinline__ unsigned int encf(float f) {
    unsigned int u = __float_as_uint(f);
    return (u & 0x80000000u) ? ~u : (u | 0x80000000u);
}
__device__ __forceinline__ float decf(unsigned int u) {
    return (u & 0x80000000u) ? __uint_as_float(u & 0x7FFFFFFFu) : __uint_as_float(~u);
}

// ---------------- merged prep kernel ----------------
__global__ __launch_bounds__(256) void prep_kernel(const float* __restrict__ ea,
                                                   const float* __restrict__ Ew,
                                                   const int* __restrict__ adj,
                                                   const float* __restrict__ W,
                                                   const unsigned int* __restrict__ maskw) {
    int blk = blockIdx.x;
    int t = threadIdx.x;
    if (blk < 64) {
        int idx = blk * 256 + t;  // i*128 + j
        float e0 = ea[idx * 2], e1 = ea[idx * 2 + 1];
        bool ok = adj[idx] != 0;
        int i = idx >> 7, j = idx & 127;
        int tidx = j * Vn + i;
        float v0 = ok ? (e0 * Ew[0] + e1 * Ew[1]) : NEGBIG;
        float v1 = ok ? (e0 * Ew[2] + e1 * Ew[3]) : NEGBIG;
        float v2 = ok ? (e0 * Ew[4] + e1 * Ew[5]) : NEGBIG;
        float v3 = ok ? (e0 * Ew[6] + e1 * Ew[7]) : NEGBIG;
        g_efm[0 * 16384 + tidx] = v0;
        g_efm[1 * 16384 + tidx] = v1;
        g_efm[2 * 16384 + tidx] = v2;
        g_efm[3 * 16384 + tidx] = v3;
        float m[4] = {v0, v1, v2, v3};
#pragma unroll
        for (int h = 0; h < 4; h++) {
            float x = m[h];
            x = fmaxf(x, __shfl_xor_sync(0xffffffffu, x, 1));
            x = fmaxf(x, __shfl_xor_sync(0xffffffffu, x, 2));
            x = fmaxf(x, __shfl_xor_sync(0xffffffffu, x, 4));
            x = fmaxf(x, __shfl_xor_sync(0xffffffffu, x, 8));
            x = fmaxf(x, __shfl_xor_sync(0xffffffffu, x, 16));
            if ((t & 31) == 0) atomicMax(&g_efgmax_u[h], encf(x));
        }
    } else if (blk < 128) {
        int gid = (blk - 64) * 256 + t;
        float4 v = ((const float4*)W)[gid];
        uint32_t h01, l01, h23, l23;
        split2(v.x, v.y, h01, l01);
        split2(v.z, v.w, h23, l23);
        ((uint2*)g_Wh)[gid] = make_uint2(h01, h23);
        ((uint2*)g_Wl)[gid] = make_uint2(l01, l23);
    } else {
        __shared__ int okInt, okFloat;
        if (t == 0) { okInt = 1; okFloat = 1; }
        __syncthreads();
        int badI = 0, badF = 0;
        for (int idx = t; idx < 16384; idx += 256) {
            unsigned int v = maskw[idx];
            if (v > 1u) badI = 1;
            if (v != 0u && v != 0x3f800000u) badF = 1;
        }
        if (badI) okInt = 0;
        if (badF) okFloat = 0;
        __syncthreads();
        if (t == 0) g_mask_mode = okFloat ? 2 : (okInt ? 1 : 0);
    }
}

// ---------------- GEMM1: Wx = x @ W^T + fused s_src/s_dst dots ----------------
#define GSTAGE 61440
#define GEMM_SMEM (2 * GSTAGE)

__global__ __launch_bounds__(512) void gemm_wx_kernel(const float* __restrict__ x,
                                                      const float* __restrict__ a) {
    extern __shared__ char gs[];
    int m0 = blockIdx.x * 128;
    int t = threadIdx.x;
    int w = t >> 5, lane = t & 31;
    int wm = w & 3, wn = w >> 2;  // warp tile 32m x 64n; 64n == one head (= wn)

    int rowoffA = ((lane >> 3) & 1) * 8 + (lane & 7);
    int coloffA = (lane >> 4) * 8;
    int rowoffB = (lane >> 4) * 8 + (lane & 7);
    int coloffB = ((lane >> 3) & 1) * 8;

    const uint4* gwh4 = (const uint4*)g_Wh;
    const uint4* gwl4 = (const uint4*)g_Wl;

    int arow0 = t >> 3, acq0 = t & 7;
    int arow1 = arow0 + 64;
    int brow0 = t >> 1, bhalf = t & 1;

    float4 ax0, ax1;
    uint4 rbh0, rbh1, rbl0, rbl1;

    float acc[2][8][4];
#pragma unroll
    for (int mt = 0; mt < 2; mt++)
#pragma unroll
        for (int nt = 0; nt < 8; nt++)
#pragma unroll
            for (int r = 0; r < 4; r++) acc[mt][nt][r] = 0.f;

#define G_LDG(k0)                                                                     \
    do {                                                                              \
        ax0 = *(const float4*)(x + (size_t)(m0 + arow0) * Dn + (k0) + acq0 * 4);      \
        ax1 = *(const float4*)(x + (size_t)(m0 + arow1) * Dn + (k0) + acq0 * 4);      \
        int bi0 = (brow0 * (Dn / 2) + ((k0) >> 1) + bhalf * 8) >> 2;                  \
        rbh0 = gwh4[bi0]; rbh1 = gwh4[bi0 + 1];                                       \
        rbl0 = gwl4[bi0]; rbl1 = gwl4[bi0 + 1];                                       \
    } while (0)

#define G_STS(s)                                                                      \
    do {                                                                              \
        char* st = gs + (s) * GSTAGE;                                                 \
        uint32_t* ah = (uint32_t*)st;                                                 \
        uint32_t* al = (uint32_t*)(st + 10240);                                       \
        uint4* bh = (uint4*)(st + 20480);                                             \
        uint4* bl = (uint4*)(st + 40960);                                             \
        uint32_t h01, l01, h23, l23;                                                  \
        split2(ax0.x, ax0.y, h01, l01); split2(ax0.z, ax0.w, h23, l23);               \
        ah[arow0 * 20 + acq0 * 2] = h01; ah[arow0 * 20 + acq0 * 2 + 1] = h23;         \
        al[arow0 * 20 + acq0 * 2] = l01; al[arow0 * 20 + acq0 * 2 + 1] = l23;         \
        split2(ax1.x, ax1.y, h01, l01); split2(ax1.z, ax1.w, h23, l23);               \
        ah[arow1 * 20 + acq0 * 2] = h01; ah[arow1 * 20 + acq0 * 2 + 1] = h23;         \
        al[arow1 * 20 + acq0 * 2] = l01; al[arow1 * 20 + acq0 * 2 + 1] = l23;         \
        bh[brow0 * 5 + bhalf * 2] = rbh0; bh[brow0 * 5 + bhalf * 2 + 1] = rbh1;       \
        bl[brow0 * 5 + bhalf * 2] = rbl0; bl[brow0 * 5 + bhalf * 2 + 1] = rbl1;       \
    } while (0)

    G_LDG(0);
    G_STS(0);
    G_LDG(32);
    __syncthreads();

    for (int ki = 0; ki < 8; ki++) {
        char* st = gs + (ki & 1) * GSTAGE;
        uint32_t aAh = sptr(st), aAl = sptr(st + 10240);
        uint32_t aBh = sptr(st + 20480), aBl = sptr(st + 40960);
#pragma unroll
        for (int ks = 0; ks < 32; ks += 16) {
            uint32_t Ah[2][4], Al[2][4];
#pragma unroll
            for (int mt = 0; mt < 2; mt++) {
                uint32_t off = (wm * 32 + mt * 16 + rowoffA) * 80 + (ks + coloffA) * 2;
                ldsm_x4(Ah[mt][0], Ah[mt][1], Ah[mt][2], Ah[mt][3], aAh + off);
                ldsm_x4(Al[mt][0], Al[mt][1], Al[mt][2], Al[mt][3], aAl + off);
            }
#pragma unroll
            for (int nb = 0; nb < 4; nb++) {
                uint32_t off = (wn * 64 + nb * 16 + rowoffB) * 80 + (ks + coloffB) * 2;
                uint32_t bh0, bh1, bh2, bh3, bl0, bl1, bl2, bl3;
                ldsm_x4(bh0, bh1, bh2, bh3, aBh + off);
                ldsm_x4(bl0, bl1, bl2, bl3, aBl + off);
#pragma unroll
                for (int mt = 0; mt < 2; mt++) {
                    mma_bf16(acc[mt][nb * 2], Ah[mt], bh0, bh1);
                    mma_bf16(acc[mt][nb * 2], Al[mt], bh0, bh1);
                    mma_bf16(acc[mt][nb * 2], Ah[mt], bl0, bl1);
                    mma_bf16(acc[mt][nb * 2 + 1], Ah[mt], bh2, bh3);
                    mma_bf16(acc[mt][nb * 2 + 1], Al[mt], bh2, bh3);
                    mma_bf16(acc[mt][nb * 2 + 1], Ah[mt], bl2, bl3);
                }
            }
        }
        __syncthreads();
        if (ki < 7) {
            G_STS((ki + 1) & 1);
            if (ki < 6) G_LDG((ki + 2) * 32);
            __syncthreads();
        }
    }

    // epilogue A: write Wx as fp16 hi/lo pairs
#pragma unroll
    for (int mt = 0; mt < 2; mt++)
#pragma unroll
        for (int nt = 0; nt < 8; nt++) {
            int row0 = m0 + wm * 32 + mt * 16 + (lane >> 2);
            int col = wn * 64 + nt * 8 + (lane & 3) * 2;
            uint32_t hi, lo;
            split2h(acc[mt][nt][0], acc[mt][nt][1], hi, lo);
            *(uint32_t*)&g_Wxh[(size_t)row0 * Dn + col] = hi;
            *(uint32_t*)&g_Wxl[(size_t)row0 * Dn + col] = lo;
            split2h(acc[mt][nt][2], acc[mt][nt][3], hi, lo);
            *(uint32_t*)&g_Wxh[(size_t)(row0 + 8) * Dn + col] = hi;
            *(uint32_t*)&g_Wxl[(size_t)(row0 + 8) * Dn + col] = lo;
        }

    // epilogue B: fp32 s_src/s_dst dots (head = wn, local dim dl)
    {
        float rs[2][2] = {{0.f, 0.f}, {0.f, 0.f}};
        float rd[2][2] = {{0.f, 0.f}, {0.f, 0.f}};
#pragma unroll
        for (int nt = 0; nt < 8; nt++) {
            int dl = nt * 8 + (lane & 3) * 2;
            float a0s = __ldg(&a[dl]),      a1s = __ldg(&a[dl + 1]);
            float a0d = __ldg(&a[64 + dl]), a1d = __ldg(&a[64 + dl + 1]);
#pragma unroll
            for (int mt = 0; mt < 2; mt++) {
                rs[mt][0] += acc[mt][nt][0] * a0s + acc[mt][nt][1] * a1s;
                rd[mt][0] += acc[mt][nt][0] * a0d + acc[mt][nt][1] * a1d;
                rs[mt][1] += acc[mt][nt][2] * a0s + acc[mt][nt][3] * a1s;
                rd[mt][1] += acc[mt][nt][2] * a0d + acc[mt][nt][3] * a1d;
            }
        }
#pragma unroll
        for (int mt = 0; mt < 2; mt++)
#pragma unroll
            for (int rh = 0; rh < 2; rh++) {
                float vs = rs[mt][rh], vd = rd[mt][rh];
                vs += __shfl_xor_sync(0xffffffffu, vs, 1);
                vs += __shfl_xor_sync(0xffffffffu, vs, 2);
                vd += __shfl_xor_sync(0xffffffffu, vd, 1);
                vd += __shfl_xor_sync(0xffffffffu, vd, 2);
                if ((lane & 3) == 0) {
                    int m = m0 + wm * 32 + mt * 16 + (lane >> 2) + rh * 8;
                    g_sS[wn * (Bn * Vn) + m] = vs;
                    g_sD[wn * (Bn * Vn) + m] = vd;
                }
            }
    }
}

// ---------------- fused attention per (b, h) ----------------
#define WSTR 72     // fp16 stride -> conflict-free ldmatrix
#define EFSTR 132   // fp32 stride for sEf: 132 mod 32 = 4 -> conflict-free quad loads
// SMEM: sEf 67584 | sWh 18432 | sWl 18432 | misc 1600
#define OFF_AWH 67584
#define OFF_AWL 86016
#define OFF_AMISC 104448
#define ATT_SMEM_BYTES 106048

__global__ __launch_bounds__(256, 2) void gat_attn_kernel(const void* __restrict__ maskp,
                                                          float* __restrict__ out) {
    extern __shared__ char smem[];
    float* sEf  = (float*)smem;
    __half* sWh = (__half*)(smem + OFF_AWH);
    __half* sWl = (__half*)(smem + OFF_AWL);
    float* sMb  = (float*)(smem + OFF_AMISC);  // 128
    float* sSrc = sMb + 128;                   // 128
    float* sDst = sMb + 256;                   // 128
    float* sMax = sMb + 384;                   // 1

    int h = blockIdx.x;
    int b = blockIdx.y;
    int t = threadIdx.x;

    const float* efT = g_efm + h * (Vn * Vn);

    // ---- cp.async stage: efm tile (64KB) + Wx tile (32KB) ----
    {
        int j = t >> 1, half = t & 1;
        const char* src = (const char*)(efT + j * Vn) + half * 256;
        uint32_t dst = sptr(sEf) + (uint32_t)(j * EFSTR * 4 + half * 256);
#pragma unroll
        for (int c = 0; c < 16; c++) CP_ASYNC16(dst + c * 16, src + c * 16);
    }
    {
        int i = t >> 1, half = t & 1;
        size_t baseByte = ((size_t)(b * Vn + i) * Dn + h * DHn) * 2 + half * 64;
        const char* srcH = (const char*)g_Wxh + baseByte;
        const char* srcL = (const char*)g_Wxl + baseByte;
        uint32_t dstH = sptr(sWh) + (uint32_t)(i * 144 + half * 64);
        uint32_t dstL = sptr(sWl) + (uint32_t)(i * 144 + half * 64);
#pragma unroll
        for (int c = 0; c < 4; c++) {
            CP_ASYNC16(dstH + c * 16, srcH + c * 16);
            CP_ASYNC16(dstL + c * 16, srcL + c * 16);
        }
    }
    CP_COMMIT();

    if (t < 128) {
        int mode = g_mask_mode;
        bool mv;
        int idx = b * Vn + t;
        if (mode == 0)      mv = ((const unsigned char*)maskp)[idx] != 0;
        else if (mode == 1) mv = ((const int*)maskp)[idx] != 0;
        else                mv = ((const float*)maskp)[idx] != 0.f;
        float mb = mv ? NEGBIG : 0.f;
        sMb[t] = mb;
        sSrc[t] = g_sS[h * (Bn * Vn) + b * Vn + t] + mb;
        sDst[t] = g_sD[h * (Bn * Vn) + b * Vn + t] + mb;
    }
    CP_WAIT0();
    __syncthreads();
    if (t < 32) {
        float m = fmaxf(fmaxf(sSrc[t], sSrc[t + 32]), fmaxf(sSrc[t + 64], sSrc[t + 96]));
        m = fmaxf(m, __shfl_xor_sync(0xffffffffu, m, 1));
        m = fmaxf(m, __shfl_xor_sync(0xffffffffu, m, 2));
        m = fmaxf(m, __shfl_xor_sync(0xffffffffu, m, 4));
        m = fmaxf(m, __shfl_xor_sync(0xffffffffu, m, 8));
        m = fmaxf(m, __shfl_xor_sync(0xffffffffu, m, 16));
        if (t == 0) sMax[0] = m;
    }
    __syncthreads();

    // ---- single pass: scores (ef from SMEM) -> p fp16 -> 2x f16 mma ----
    int w = t >> 5, lane = t & 31;
    int q = lane >> 2, cpos = (lane & 3) * 2;
    int j0 = w * 16 + q;
    int j1 = j0 + 8;

    float dst0 = sDst[j0], dst1 = sDst[j1];
    float maxSrcV = sMax[0];
    float efg = decf(g_efgmax_u[h]);
    float m0v = lrelu(maxSrcV + dst0 + efg);
    float m1v = lrelu(maxSrcV + dst1 + efg);

    const float* ef0 = sEf + j0 * EFSTR;
    const float* ef1 = sEf + j1 * EFSTR;

    int rowoffBt = ((lane >> 3) & 1) * 8 + (lane & 7);
    int coloffBt = (lane >> 4) * 8;
    uint32_t aWh = sptr(sWh), aWl = sptr(sWl);

    float acc[8][4];
#pragma unroll
    for (int nt = 0; nt < 8; nt++)
#pragma unroll
        for (int r = 0; r < 4; r++) acc[nt][r] = 0.f;

    float s0 = 0.f, s1 = 0.f;
#pragma unroll
    for (int k0 = 0; k0 < 8; k0++) {
        int ib = k0 * 16 + cpos;
        float2 sA = *(const float2*)&sSrc[ib];
        float2 sB = *(const float2*)&sSrc[ib + 8];
        float2 eA0 = *(const float2*)&ef0[ib];
        float2 eB0 = *(const float2*)&ef0[ib + 8];
        float2 eA1 = *(const float2*)&ef1[ib];
        float2 eB1 = *(const float2*)&ef1[ib + 8];
        float p00 = __expf(lrelu(sA.x + dst0 + eA0.x) - m0v);
        float p01 = __expf(lrelu(sA.y + dst0 + eA0.y) - m0v);
        float p02 = __expf(lrelu(sB.x + dst0 + eB0.x) - m0v);
        float p03 = __expf(lrelu(sB.y + dst0 + eB0.y) - m0v);
        float p10 = __expf(lrelu(sA.x + dst1 + eA1.x) - m1v);
        float p11 = __expf(lrelu(sA.y + dst1 + eA1.y) - m1v);
        float p12 = __expf(lrelu(sB.x + dst1 + eB1.x) - m1v);
        float p13 = __expf(lrelu(sB.y + dst1 + eB1.y) - m1v);
        s0 += p00 + p01 + p02 + p03;
        s1 += p10 + p11 + p12 + p13;
        uint32_t A[4];
        {
            __half2 t0 = __floats2half2_rn(p00, p01);
            __half2 t1 = __floats2half2_rn(p10, p11);
            __half2 t2 = __floats2half2_rn(p02, p03);
            __half2 t3 = __floats2half2_rn(p12, p13);
            A[0] = *(uint32_t*)&t0;
            A[1] = *(uint32_t*)&t1;
            A[2] = *(uint32_t*)&t2;
            A[3] = *(uint32_t*)&t3;
        }
#pragma unroll
        for (int nc = 0; nc < 4; nc++) {
            uint32_t offB = ((k0 * 16 + rowoffBt) * WSTR + nc * 16 + coloffBt) * 2;
            uint32_t bh0, bh1, bh2, bh3, bl0, bl1, bl2, bl3;
            ldsm_x4_t(bh0, bh1, bh2, bh3, aWh + offB);
            ldsm_x4_t(bl0, bl1, bl2, bl3, aWl + offB);
            mma_f16(acc[nc * 2], A, bh0, bh1);
            mma_f16(acc[nc * 2], A, bl0, bl1);
            mma_f16(acc[nc * 2 + 1], A, bh2, bh3);
            mma_f16(acc[nc * 2 + 1], A, bl2, bl3);
        }
    }
    s0 += __shfl_xor_sync(0xffffffffu, s0, 1);
    s0 += __shfl_xor_sync(0xffffffffu, s0, 2);
    s1 += __shfl_xor_sync(0xffffffffu, s1, 1);
    s1 += __shfl_xor_sync(0xffffffffu, s1, 2);
    float inv0 = 1.0f / s0;
    float inv1 = 1.0f / s1;

    bool msk0 = (sMb[j0] != 0.f);
    bool msk1 = (sMb[j1] != 0.f);
#pragma unroll
    for (int nt = 0; nt < 8; nt++) {
        int dd = nt * 8 + cpos;
        {
            float v0 = acc[nt][0] * inv0;
            float v1 = acc[nt][1] * inv0;
            float2 o;
            o.x = msk0 ? 0.f : (v0 > 0.f ? v0 : __expf(v0) - 1.f);
            o.y = msk0 ? 0.f : (v1 > 0.f ? v1 : __expf(v1) - 1.f);
            *(float2*)(out + (size_t)(b * Vn + j0) * Dn + h * DHn + dd) = o;
        }
        {
            float v0 = acc[nt][2] * inv1;
            float v1 = acc[nt][3] * inv1;
            float2 o;
            o.x = msk1 ? 0.f : (v0 > 0.f ? v0 : __expf(v0) - 1.f);
            o.y = msk1 ? 0.f : (v1 > 0.f ? v1 : __expf(v1) - 1.f);
            *(float2*)(out + (size_t)(b * Vn + j1) * Dn + h * DHn + dd) = o;
        }
    }
}

// ---------------- launch ----------------
extern "C" void kernel_launch(void* const* d_in, const int* in_sizes, int n_in,
                              void* d_out, int out_size) {
    const float* x    = (const float*)d_in[0];
    const int*   adj  = (const int*)d_in[1];
    const float* ea   = (const float*)d_in[2];
    const void*  mask = (const void*)d_in[3];
    const float* W    = (const float*)d_in[4];
    const float* a    = (const float*)d_in[5];
    const float* Ew   = (const float*)d_in[6];
    float* out = (float*)d_out;

    cudaFuncSetAttribute(gat_attn_kernel, cudaFuncAttributeMaxDynamicSharedMemorySize,
                         ATT_SMEM_BYTES);
    cudaFuncSetAttribute(gemm_wx_kernel, cudaFuncAttributeMaxDynamicSharedMemorySize,
                         GEMM_SMEM);

    prep_kernel<<<129, 256>>>(ea, Ew, adj, W, (const unsigned int*)mask);
    gemm_wx_kernel<<<(Bn * Vn) / 128, 512, GEMM_SMEM>>>(x, a);
    gat_attn_kernel<<<dim3(Hn, Bn), 256, ATT_SMEM_BYTES>>>(mask, out);
}

// round 16
// speedup vs baseline: 1.0974x; 1.0974x over previous
#include <cuda_runtime.h>
#include <cuda_bf16.h>
#include <cuda_fp16.h>
#include <math.h>
#include <stdint.h>

#define Bn 512
#define Vn 128
#define Dn 256
#define Hn 4
#define DHn 64

// ---------------- scratch (no cudaMalloc allowed) ----------------
__device__ __nv_bfloat16 g_Wh[Dn * Dn];         // W hi (bf16, gemm internal)
__device__ __nv_bfloat16 g_Wl[Dn * Dn];         // W lo
__device__ __half g_Wxh[(size_t)Bn * Vn * Dn];  // Wx hi (fp16)
__device__ __half g_Wxl[(size_t)Bn * Vn * Dn];  // Wx lo (fp16)
__device__ float g_sS[Hn * Bn * Vn];            // [h][b*V+i] s_src (fp32, from gemm)
__device__ float g_sD[Hn * Bn * Vn];            // [h][b*V+i] s_dst
__device__ float g_efm[Hn * Vn * Vn];           // TRANSPOSED: [h][j][i] = adj? ef : -1e30
__device__ unsigned int g_efgmax_u[Hn];         // encoded per-head global max
__device__ int   g_mask_mode;                   // 0=u8, 1=i32, 2=f32

#define NEGBIG (-1e30f)

// ---------------- helpers ----------------
__device__ __forceinline__ void mma_bf16(float* c, const uint32_t* a, uint32_t b0, uint32_t b1) {
    asm volatile(
        "mma.sync.aligned.m16n8k16.row.col.f32.bf16.bf16.f32 "
        "{%0,%1,%2,%3},{%4,%5,%6,%7},{%8,%9},{%0,%1,%2,%3};"
        : "+f"(c[0]), "+f"(c[1]), "+f"(c[2]), "+f"(c[3])
        : "r"(a[0]), "r"(a[1]), "r"(a[2]), "r"(a[3]), "r"(b0), "r"(b1));
}
__device__ __forceinline__ void mma_f16(float* c, const uint32_t* a, uint32_t b0, uint32_t b1) {
    asm volatile(
        "mma.sync.aligned.m16n8k16.row.col.f32.f16.f16.f32 "
        "{%0,%1,%2,%3},{%4,%5,%6,%7},{%8,%9},{%0,%1,%2,%3};"
        : "+f"(c[0]), "+f"(c[1]), "+f"(c[2]), "+f"(c[3])
        : "r"(a[0]), "r"(a[1]), "r"(a[2]), "r"(a[3]), "r"(b0), "r"(b1));
}

__device__ __forceinline__ void ldsm_x4(uint32_t& r0, uint32_t& r1, uint32_t& r2, uint32_t& r3,
                                        uint32_t addr) {
    asm volatile("ldmatrix.sync.aligned.m8n8.x4.shared.b16 {%0,%1,%2,%3}, [%4];"
                 : "=r"(r0), "=r"(r1), "=r"(r2), "=r"(r3) : "r"(addr));
}
__device__ __forceinline__ void ldsm_x4_t(uint32_t& r0, uint32_t& r1, uint32_t& r2, uint32_t& r3,
                                          uint32_t addr) {
    asm volatile("ldmatrix.sync.aligned.m8n8.x4.trans.shared.b16 {%0,%1,%2,%3}, [%4];"
                 : "=r"(r0), "=r"(r1), "=r"(r2), "=r"(r3) : "r"(addr));
}
__device__ __forceinline__ uint32_t sptr(const void* p) {
    return (uint32_t)__cvta_generic_to_shared(p);
}

// bf16 hi/lo split (gemm internal)
__device__ __forceinline__ void split2(float a, float b, uint32_t& hi, uint32_t& lo) {
    __nv_bfloat16 ha = __float2bfloat16_rn(a);
    __nv_bfloat16 hb = __float2bfloat16_rn(b);
    float ra = a - __bfloat162float(ha);
    float rb = b - __bfloat162float(hb);
    __nv_bfloat162 vh; vh.x = ha; vh.y = hb;
    __nv_bfloat162 vl; vl.x = __float2bfloat16_rn(ra); vl.y = __float2bfloat16_rn(rb);
    hi = *reinterpret_cast<uint32_t*>(&vh);
    lo = *reinterpret_cast<uint32_t*>(&vl);
}

// fp16 hi/lo split (Wx storage)
__device__ __forceinline__ void split2h(float a, float b, uint32_t& hi, uint32_t& lo) {
    __half2 vh = __floats2half2_rn(a, b);
    float ra = a - __half2float(vh.x);
    float rb = b - __half2float(vh.y);
    __half2 vl = __floats2half2_rn(ra, rb);
    hi = *reinterpret_cast<uint32_t*>(&vh);
    lo = *reinterpret_cast<uint32_t*>(&vl);
}

__device__ __forceinline__ float lrelu(float s) { return (s >= 0.f) ? s : 0.2f * s; }

__device__ __forceinline__ unsigned int encf(float f) {
    unsigned int u = __float_as_uint(f);
    return (u & 0x80000000u) ? ~u : (u | 0x80000000u);
}
__device__ __forceinline__ float decf(unsigned int u) {
    return (u & 0x80000000u) ? __uint_as_float(u & 0x7FFFFFFFu) : __uint_as_float(~u);
}

// ---------------- merged prep kernel ----------------
__global__ __launch_bounds__(256) void prep_kernel(const float* __restrict__ ea,
                                                   const float* __restrict__ Ew,
                                                   const int* __restrict__ adj,
                                                   const float* __restrict__ W,
                                                   const unsigned int* __restrict__ maskw) {
    int blk = blockIdx.x;
    int t = threadIdx.x;
    if (blk < 64) {
        int idx = blk * 256 + t;  // i*128 + j
        float e0 = ea[idx * 2], e1 = ea[idx * 2 + 1];
        bool ok = adj[idx] != 0;
        int i = idx >> 7, j = idx & 127;
        int tidx = j * Vn + i;
        float v0 = ok ? (e0 * Ew[0] + e1 * Ew[1]) : NEGBIG;
        float v1 = ok ? (e0 * Ew[2] + e1 * Ew[3]) : NEGBIG;
        float v2 = ok ? (e0 * Ew[4] + e1 * Ew[5]) : NEGBIG;
        float v3 = ok ? (e0 * Ew[6] + e1 * Ew[7]) : NEGBIG;
        g_efm[0 * 16384 + tidx] = v0;
        g_efm[1 * 16384 + tidx] = v1;
        g_efm[2 * 16384 + tidx] = v2;
        g_efm[3 * 16384 + tidx] = v3;
        float m[4] = {v0, v1, v2, v3};
#pragma unroll
        for (int h = 0; h < 4; h++) {
            float x = m[h];
            x = fmaxf(x, __shfl_xor_sync(0xffffffffu, x, 1));
            x = fmaxf(x, __shfl_xor_sync(0xffffffffu, x, 2));
            x = fmaxf(x, __shfl_xor_sync(0xffffffffu, x, 4));
            x = fmaxf(x, __shfl_xor_sync(0xffffffffu, x, 8));
            x = fmaxf(x, __shfl_xor_sync(0xffffffffu, x, 16));
            if ((t & 31) == 0) atomicMax(&g_efgmax_u[h], encf(x));
        }
    } else if (blk < 128) {
        int gid = (blk - 64) * 256 + t;
        float4 v = ((const float4*)W)[gid];
        uint32_t h01, l01, h23, l23;
        split2(v.x, v.y, h01, l01);
        split2(v.z, v.w, h23, l23);
        ((uint2*)g_Wh)[gid] = make_uint2(h01, h23);
        ((uint2*)g_Wl)[gid] = make_uint2(l01, l23);
    } else {
        __shared__ int okInt, okFloat;
        if (t == 0) { okInt = 1; okFloat = 1; }
        __syncthreads();
        int badI = 0, badF = 0;
        for (int idx = t; idx < 16384; idx += 256) {
            unsigned int v = maskw[idx];
            if (v > 1u) badI = 1;
            if (v != 0u && v != 0x3f800000u) badF = 1;
        }
        if (badI) okInt = 0;
        if (badF) okFloat = 0;
        __syncthreads();
        if (t == 0) g_mask_mode = okFloat ? 2 : (okInt ? 1 : 0);
    }
}

// ---------------- GEMM1: Wx = x @ W^T + fused s_src/s_dst dots ----------------
#define GSTAGE 61440
#define GEMM_SMEM (2 * GSTAGE)

__global__ __launch_bounds__(512) void gemm_wx_kernel(const float* __restrict__ x,
                                                      const float* __restrict__ a) {
    extern __shared__ char gs[];
    int m0 = blockIdx.x * 128;
    int t = threadIdx.x;
    int w = t >> 5, lane = t & 31;
    int wm = w & 3, wn = w >> 2;  // warp tile 32m x 64n; 64n == one head (= wn)

    int rowoffA = ((lane >> 3) & 1) * 8 + (lane & 7);
    int coloffA = (lane >> 4) * 8;
    int rowoffB = (lane >> 4) * 8 + (lane & 7);
    int coloffB = ((lane >> 3) & 1) * 8;

    const uint4* gwh4 = (const uint4*)g_Wh;
    const uint4* gwl4 = (const uint4*)g_Wl;

    int arow0 = t >> 3, acq0 = t & 7;
    int arow1 = arow0 + 64;
    int brow0 = t >> 1, bhalf = t & 1;

    float4 ax0, ax1;
    uint4 rbh0, rbh1, rbl0, rbl1;

    float acc[2][8][4];
#pragma unroll
    for (int mt = 0; mt < 2; mt++)
#pragma unroll
        for (int nt = 0; nt < 8; nt++)
#pragma unroll
            for (int r = 0; r < 4; r++) acc[mt][nt][r] = 0.f;

#define G_LDG(k0)                                                                     \
    do {                                                                              \
        ax0 = *(const float4*)(x + (size_t)(m0 + arow0) * Dn + (k0) + acq0 * 4);      \
        ax1 = *(const float4*)(x + (size_t)(m0 + arow1) * Dn + (k0) + acq0 * 4);      \
        int bi0 = (brow0 * (Dn / 2) + ((k0) >> 1) + bhalf * 8) >> 2;                  \
        rbh0 = gwh4[bi0]; rbh1 = gwh4[bi0 + 1];                                       \
        rbl0 = gwl4[bi0]; rbl1 = gwl4[bi0 + 1];                                       \
    } while (0)

#define G_STS(s)                                                                      \
    do {                                                                              \
        char* st = gs + (s) * GSTAGE;                                                 \
        uint32_t* ah = (uint32_t*)st;                                                 \
        uint32_t* al = (uint32_t*)(st + 10240);                                       \
        uint4* bh = (uint4*)(st + 20480);                                             \
        uint4* bl = (uint4*)(st + 40960);                                             \
        uint32_t h01, l01, h23, l23;                                                  \
        split2(ax0.x, ax0.y, h01, l01); split2(ax0.z, ax0.w, h23, l23);               \
        ah[arow0 * 20 + acq0 * 2] = h01; ah[arow0 * 20 + acq0 * 2 + 1] = h23;         \
        al[arow0 * 20 + acq0 * 2] = l01; al[arow0 * 20 + acq0 * 2 + 1] = l23;         \
        split2(ax1.x, ax1.y, h01, l01); split2(ax1.z, ax1.w, h23, l23);               \
        ah[arow1 * 20 + acq0 * 2] = h01; ah[arow1 * 20 + acq0 * 2 + 1] = h23;         \
        al[arow1 * 20 + acq0 * 2] = l01; al[arow1 * 20 + acq0 * 2 + 1] = l23;         \
        bh[brow0 * 5 + bhalf * 2] = rbh0; bh[brow0 * 5 + bhalf * 2 + 1] = rbh1;       \
        bl[brow0 * 5 + bhalf * 2] = rbl0; bl[brow0 * 5 + bhalf * 2 + 1] = rbl1;       \
    } while (0)

    G_LDG(0);
    G_STS(0);
    G_LDG(32);
    __syncthreads();

    for (int ki = 0; ki < 8; ki++) {
        char* st = gs + (ki & 1) * GSTAGE;
        uint32_t aAh = sptr(st), aAl = sptr(st + 10240);
        uint32_t aBh = sptr(st + 20480), aBl = sptr(st + 40960);
#pragma unroll
        for (int ks = 0; ks < 32; ks += 16) {
            uint32_t Ah[2][4], Al[2][4];
#pragma unroll
            for (int mt = 0; mt < 2; mt++) {
                uint32_t off = (wm * 32 + mt * 16 + rowoffA) * 80 + (ks + coloffA) * 2;
                ldsm_x4(Ah[mt][0], Ah[mt][1], Ah[mt][2], Ah[mt][3], aAh + off);
                ldsm_x4(Al[mt][0], Al[mt][1], Al[mt][2], Al[mt][3], aAl + off);
            }
#pragma unroll
            for (int nb = 0; nb < 4; nb++) {
                uint32_t off = (wn * 64 + nb * 16 + rowoffB) * 80 + (ks + coloffB) * 2;
                uint32_t bh0, bh1, bh2, bh3, bl0, bl1, bl2, bl3;
                ldsm_x4(bh0, bh1, bh2, bh3, aBh + off);
                ldsm_x4(bl0, bl1, bl2, bl3, aBl + off);
#pragma unroll
                for (int mt = 0; mt < 2; mt++) {
                    mma_bf16(acc[mt][nb * 2], Ah[mt], bh0, bh1);
                    mma_bf16(acc[mt][nb * 2], Al[mt], bh0, bh1);
                    mma_bf16(acc[mt][nb * 2], Ah[mt], bl0, bl1);
                    mma_bf16(acc[mt][nb * 2 + 1], Ah[mt], bh2, bh3);
                    mma_bf16(acc[mt][nb * 2 + 1], Al[mt], bh2, bh3);
                    mma_bf16(acc[mt][nb * 2 + 1], Ah[mt], bl2, bl3);
                }
            }
        }
        __syncthreads();
        if (ki < 7) {
            G_STS((ki + 1) & 1);
            if (ki < 6) G_LDG((ki + 2) * 32);
            __syncthreads();
        }
    }

    // epilogue A: write Wx as fp16 hi/lo pairs
#pragma unroll
    for (int mt = 0; mt < 2; mt++)
#pragma unroll
        for (int nt = 0; nt < 8; nt++) {
            int row0 = m0 + wm * 32 + mt * 16 + (lane >> 2);
            int col = wn * 64 + nt * 8 + (lane & 3) * 2;
            uint32_t hi, lo;
            split2h(acc[mt][nt][0], acc[mt][nt][1], hi, lo);
            *(uint32_t*)&g_Wxh[(size_t)row0 * Dn + col] = hi;
            *(uint32_t*)&g_Wxl[(size_t)row0 * Dn + col] = lo;
            split2h(acc[mt][nt][2], acc[mt][nt][3], hi, lo);
            *(uint32_t*)&g_Wxh[(size_t)(row0 + 8) * Dn + col] = hi;
            *(uint32_t*)&g_Wxl[(size_t)(row0 + 8) * Dn + col] = lo;
        }

    // epilogue B: fp32 s_src/s_dst dots (head = wn, local dim dl)
    {
        float rs[2][2] = {{0.f, 0.f}, {0.f, 0.f}};
        float rd[2][2] = {{0.f, 0.f}, {0.f, 0.f}};
#pragma unroll
        for (int nt = 0; nt < 8; nt++) {
            int dl = nt * 8 + (lane & 3) * 2;
            float a0s = __ldg(&a[dl]),      a1s = __ldg(&a[dl + 1]);
            float a0d = __ldg(&a[64 + dl]), a1d = __ldg(&a[64 + dl + 1]);
#pragma unroll
            for (int mt = 0; mt < 2; mt++) {
                rs[mt][0] += acc[mt][nt][0] * a0s + acc[mt][nt][1] * a1s;
                rd[mt][0] += acc[mt][nt][0] * a0d + acc[mt][nt][1] * a1d;
                rs[mt][1] += acc[mt][nt][2] * a0s + acc[mt][nt][3] * a1s;
                rd[mt][1] += acc[mt][nt][2] * a0d + acc[mt][nt][3] * a1d;
            }
        }
#pragma unroll
        for (int mt = 0; mt < 2; mt++)
#pragma unroll
            for (int rh = 0; rh < 2; rh++) {
                float vs = rs[mt][rh], vd = rd[mt][rh];
                vs += __shfl_xor_sync(0xffffffffu, vs, 1);
                vs += __shfl_xor_sync(0xffffffffu, vs, 2);
                vd += __shfl_xor_sync(0xffffffffu, vd, 1);
                vd += __shfl_xor_sync(0xffffffffu, vd, 2);
                if ((lane & 3) == 0) {
                    int m = m0 + wm * 32 + mt * 16 + (lane >> 2) + rh * 8;
                    g_sS[wn * (Bn * Vn) + m] = vs;
                    g_sD[wn * (Bn * Vn) + m] = vd;
                }
            }
    }
}

// ---------------- fused attention per (b, h) ----------------
#define WSTR 72  // fp16 stride -> conflict-free ldmatrix
// SMEM: sWh 18432 | sWl 18432 | misc floats 385
#define ATT_SMEM_BYTES 38464

__global__ __launch_bounds__(256, 4) void gat_attn_kernel(const void* __restrict__ maskp,
                                                          float* __restrict__ out) {
    extern __shared__ char smem[];
    __half* sWh = (__half*)smem;
    __half* sWl = (__half*)(smem + 18432);
    float* sMb  = (float*)(smem + 36864);  // 128
    float* sSrc = sMb + 128;               // 128
    float* sDst = sMb + 256;               // 128
    float* sMax = sMb + 384;               // 1

    int h = blockIdx.x;
    int b = blockIdx.y;
    int t = threadIdx.x;

    if (t < 128) {
        int mode = g_mask_mode;
        bool mv;
        int idx = b * Vn + t;
        if (mode == 0)      mv = ((const unsigned char*)maskp)[idx] != 0;
        else if (mode == 1) mv = ((const int*)maskp)[idx] != 0;
        else                mv = ((const float*)maskp)[idx] != 0.f;
        float mb = mv ? NEGBIG : 0.f;
        sMb[t] = mb;
        sSrc[t] = g_sS[h * (Bn * Vn) + b * Vn + t] + mb;
        sDst[t] = g_sD[h * (Bn * Vn) + b * Vn + t] + mb;
    }

    // ---- pure copy: Wx[b,:,h,:] fp16 hi/lo -> SMEM [i][d] (4x STS.128 each) ----
    {
        int i = t >> 1, half = t & 1;
        size_t base32 = (((size_t)(b * Vn + i) * Dn + h * DHn) >> 1) + half * 16;
        const uint4* ph4 = (const uint4*)((const uint32_t*)g_Wxh + base32);
        const uint4* pl4 = (const uint4*)((const uint32_t*)g_Wxl + base32);
        uint4* wh4 = (uint4*)sWh;
        uint4* wl4 = (uint4*)sWl;
        int di = i * 9 + half * 4;  // 9 uint4 per row (72 bf16)
#pragma unroll
        for (int k = 0; k < 4; k++) {
            wh4[di + k] = ph4[k];
            wl4[di + k] = pl4[k];
        }
    }
    __syncthreads();
    if (t < 32) {
        float m = fmaxf(fmaxf(sSrc[t], sSrc[t + 32]), fmaxf(sSrc[t + 64], sSrc[t + 96]));
        m = fmaxf(m, __shfl_xor_sync(0xffffffffu, m, 1));
        m = fmaxf(m, __shfl_xor_sync(0xffffffffu, m, 2));
        m = fmaxf(m, __shfl_xor_sync(0xffffffffu, m, 4));
        m = fmaxf(m, __shfl_xor_sync(0xffffffffu, m, 8));
        m = fmaxf(m, __shfl_xor_sync(0xffffffffu, m, 16));
        if (t == 0) sMax[0] = m;
    }
    __syncthreads();

    // ---- single pass: scores -> p = exp(e - m_ub) fp16 -> 2x f16 mma ----
    int w = t >> 5, lane = t & 31;
    int q = lane >> 2, cpos = (lane & 3) * 2;
    int j0 = w * 16 + q;
    int j1 = j0 + 8;

    float dst0 = sDst[j0], dst1 = sDst[j1];
    {
        float maxSrcV = sMax[0];
        float efg = decf(g_efgmax_u[h]);
        float mu0 = lrelu(maxSrcV + dst0 + efg);
        float mu1 = lrelu(maxSrcV + dst1 + efg);
        dst0 -= 0.f;  // keep dst0/dst1 live
        // store bounds in registers below
        // (scoped to limit live range of maxSrcV/efg)
        // fallthrough via variables:
        // m0v/m1v declared next
        __builtin_assume(true);
        // re-declare outside scope:
        // (handled by assigning to outer vars)
        // --- outer vars:
        // (see below)
        // NOTE: compiler-friendly pattern
        sMax[1 + (t & 0)] = sMax[1];  // no-op touch removed by compiler
        // assign:
        *(&dst0) = dst0;  // no-op
        // actual bound vars:
        // declared after this block
        // (we simply recompute cheaply instead)
        (void)mu0; (void)mu1;
    }
    float m0v = lrelu(sMax[0] + dst0 + decf(g_efgmax_u[h]));
    float m1v = lrelu(sMax[0] + dst1 + decf(g_efgmax_u[h]));

    const float* ef0 = g_efm + h * (Vn * Vn) + j0 * Vn;
    const float* ef1 = g_efm + h * (Vn * Vn) + j1 * Vn;

    int rowoffBt = ((lane >> 3) & 1) * 8 + (lane & 7);
    int coloffBt = (lane >> 4) * 8;
    uint32_t aWh = sptr(sWh), aWl = sptr(sWl);

    float acc[8][4];
#pragma unroll
    for (int nt = 0; nt < 8; nt++)
#pragma unroll
        for (int r = 0; r < 4; r++) acc[nt][r] = 0.f;

    float s0 = 0.f, s1 = 0.f;
#pragma unroll
    for (int k0 = 0; k0 < 8; k0++) {
        int ib = k0 * 16 + cpos;
        float2 sA = *(const float2*)&sSrc[ib];
        float2 sB = *(const float2*)&sSrc[ib + 8];
        float2 eA0 = *(const float2*)&ef0[ib];
        float2 eB0 = *(const float2*)&ef0[ib + 8];
        float2 eA1 = *(const float2*)&ef1[ib];
        float2 eB1 = *(const float2*)&ef1[ib + 8];
        float p00 = __expf(lrelu(sA.x + dst0 + eA0.x) - m0v);
        float p01 = __expf(lrelu(sA.y + dst0 + eA0.y) - m0v);
        float p02 = __expf(lrelu(sB.x + dst0 + eB0.x) - m0v);
        float p03 = __expf(lrelu(sB.y + dst0 + eB0.y) - m0v);
        float p10 = __expf(lrelu(sA.x + dst1 + eA1.x) - m1v);
        float p11 = __expf(lrelu(sA.y + dst1 + eA1.y) - m1v);
        float p12 = __expf(lrelu(sB.x + dst1 + eB1.x) - m1v);
        float p13 = __expf(lrelu(sB.y + dst1 + eB1.y) - m1v);
        s0 += p00 + p01 + p02 + p03;
        s1 += p10 + p11 + p12 + p13;
        uint32_t A[4];
        {
            __half2 t0 = __floats2half2_rn(p00, p01);
            __half2 t1 = __floats2half2_rn(p10, p11);
            __half2 t2 = __floats2half2_rn(p02, p03);
            __half2 t3 = __floats2half2_rn(p12, p13);
            A[0] = *(uint32_t*)&t0;
            A[1] = *(uint32_t*)&t1;
            A[2] = *(uint32_t*)&t2;
            A[3] = *(uint32_t*)&t3;
        }
#pragma unroll
        for (int nc = 0; nc < 4; nc++) {
            uint32_t offB = ((k0 * 16 + rowoffBt) * WSTR + nc * 16 + coloffBt) * 2;
            uint32_t bh0, bh1, bh2, bh3, bl0, bl1, bl2, bl3;
            ldsm_x4_t(bh0, bh1, bh2, bh3, aWh + offB);
            ldsm_x4_t(bl0, bl1, bl2, bl3, aWl + offB);
            mma_f16(acc[nc * 2], A, bh0, bh1);
            mma_f16(acc[nc * 2], A, bl0, bl1);
            mma_f16(acc[nc * 2 + 1], A, bh2, bh3);
            mma_f16(acc[nc * 2 + 1], A, bl2, bl3);
        }
    }
    s0 += __shfl_xor_sync(0xffffffffu, s0, 1);
    s0 += __shfl_xor_sync(0xffffffffu, s0, 2);
    s1 += __shfl_xor_sync(0xffffffffu, s1, 1);
    s1 += __shfl_xor_sync(0xffffffffu, s1, 2);
    float inv0 = 1.0f / s0;
    float inv1 = 1.0f / s1;

    bool msk0 = (sMb[j0] != 0.f);
    bool msk1 = (sMb[j1] != 0.f);
    float* out0 = out + (size_t)(b * Vn + j0) * Dn + h * DHn + cpos;
    float* out1 = out + (size_t)(b * Vn + j1) * Dn + h * DHn + cpos;
#pragma unroll
    for (int nt = 0; nt < 8; nt++) {
        {
            float v0 = acc[nt][0] * inv0;
            float v1 = acc[nt][1] * inv0;
            float2 o;
            o.x = msk0 ? 0.f : (v0 > 0.f ? v0 : __expf(v0) - 1.f);
            o.y = msk0 ? 0.f : (v1 > 0.f ? v1 : __expf(v1) - 1.f);
            *(float2*)(out0 + nt * 8) = o;
        }
        {
            float v0 = acc[nt][2] * inv1;
            float v1 = acc[nt][3] * inv1;
            float2 o;
            o.x = msk1 ? 0.f : (v0 > 0.f ? v0 : __expf(v0) - 1.f);
            o.y = msk1 ? 0.f : (v1 > 0.f ? v1 : __expf(v1) - 1.f);
            *(float2*)(out1 + nt * 8) = o;
        }
    }
}

// ---------------- launch ----------------
extern "C" void kernel_launch(void* const* d_in, const int* in_sizes, int n_in,
                              void* d_out, int out_size) {
    const float* x    = (const float*)d_in[0];
    const int*   adj  = (const int*)d_in[1];
    const float* ea   = (const float*)d_in[2];
    const void*  mask = (const void*)d_in[3];
    const float* W    = (const float*)d_in[4];
    const float* a    = (const float*)d_in[5];
    const float* Ew   = (const float*)d_in[6];
    float* out = (float*)d_out;

    cudaFuncSetAttribute(gat_attn_kernel, cudaFuncAttributeMaxDynamicSharedMemorySize,
                         ATT_SMEM_BYTES);
    cudaFuncSetAttribute(gemm_wx_kernel, cudaFuncAttributeMaxDynamicSharedMemorySize,
                         GEMM_SMEM);

    prep_kernel<<<129, 256>>>(ea, Ew, adj, W, (const unsigned int*)mask);
    gemm_wx_kernel<<<(Bn * Vn) / 128, 512, GEMM_SMEM>>>(x, a);
    gat_attn_kernel<<<dim3(Hn, Bn), 256, ATT_SMEM_BYTES>>>(mask, out);
}

// round 17
// speedup vs baseline: 1.2742x; 1.1611x over previous
#include <cuda_runtime.h>
#include <cuda_bf16.h>
#include <cuda_fp16.h>
#include <math.h>
#include <stdint.h>

#define Bn 512
#define Vn 128
#define Dn 256
#define Hn 4
#define DHn 64

// ---------------- scratch (no cudaMalloc allowed) ----------------
__device__ __nv_bfloat16 g_Wh[Dn * Dn];         // W hi (bf16, gemm internal)
__device__ __nv_bfloat16 g_Wl[Dn * Dn];         // W lo
__device__ __half g_Wxh[(size_t)Bn * Vn * Dn];  // Wx (fp16, single precision copy; 67MB -> L2-resident)
__device__ float g_sS[Hn * Bn * Vn];            // [h][b*V+i] s_src (fp32, from gemm)
__device__ float g_sD[Hn * Bn * Vn];            // [h][b*V+i] s_dst
__device__ float g_efm[Hn * Vn * Vn];           // TRANSPOSED: [h][j][i] = adj? ef : -1e30
__device__ unsigned int g_efgmax_u[Hn];         // encoded per-head global max
__device__ int   g_mask_mode;                   // 0=u8, 1=i32, 2=f32

#define NEGBIG (-1e30f)

// ---------------- helpers ----------------
__device__ __forceinline__ void mma_bf16(float* c, const uint32_t* a, uint32_t b0, uint32_t b1) {
    asm volatile(
        "mma.sync.aligned.m16n8k16.row.col.f32.bf16.bf16.f32 "
        "{%0,%1,%2,%3},{%4,%5,%6,%7},{%8,%9},{%0,%1,%2,%3};"
        : "+f"(c[0]), "+f"(c[1]), "+f"(c[2]), "+f"(c[3])
        : "r"(a[0]), "r"(a[1]), "r"(a[2]), "r"(a[3]), "r"(b0), "r"(b1));
}
__device__ __forceinline__ void mma_f16(float* c, const uint32_t* a, uint32_t b0, uint32_t b1) {
    asm volatile(
        "mma.sync.aligned.m16n8k16.row.col.f32.f16.f16.f32 "
        "{%0,%1,%2,%3},{%4,%5,%6,%7},{%8,%9},{%0,%1,%2,%3};"
        : "+f"(c[0]), "+f"(c[1]), "+f"(c[2]), "+f"(c[3])
        : "r"(a[0]), "r"(a[1]), "r"(a[2]), "r"(a[3]), "r"(b0), "r"(b1));
}

__device__ __forceinline__ void ldsm_x4(uint32_t& r0, uint32_t& r1, uint32_t& r2, uint32_t& r3,
                                        uint32_t addr) {
    asm volatile("ldmatrix.sync.aligned.m8n8.x4.shared.b16 {%0,%1,%2,%3}, [%4];"
                 : "=r"(r0), "=r"(r1), "=r"(r2), "=r"(r3) : "r"(addr));
}
__device__ __forceinline__ void ldsm_x4_t(uint32_t& r0, uint32_t& r1, uint32_t& r2, uint32_t& r3,
                                          uint32_t addr) {
    asm volatile("ldmatrix.sync.aligned.m8n8.x4.trans.shared.b16 {%0,%1,%2,%3}, [%4];"
                 : "=r"(r0), "=r"(r1), "=r"(r2), "=r"(r3) : "r"(addr));
}
__device__ __forceinline__ uint32_t sptr(const void* p) {
    return (uint32_t)__cvta_generic_to_shared(p);
}

// bf16 hi/lo split (gemm internal)
__device__ __forceinline__ void split2(float a, float b, uint32_t& hi, uint32_t& lo) {
    __nv_bfloat16 ha = __float2bfloat16_rn(a);
    __nv_bfloat16 hb = __float2bfloat16_rn(b);
    float ra = a - __bfloat162float(ha);
    float rb = b - __bfloat162float(hb);
    __nv_bfloat162 vh; vh.x = ha; vh.y = hb;
    __nv_bfloat162 vl; vl.x = __float2bfloat16_rn(ra); vl.y = __float2bfloat16_rn(rb);
    hi = *reinterpret_cast<uint32_t*>(&vh);
    lo = *reinterpret_cast<uint32_t*>(&vl);
}

__device__ __forceinline__ float lrelu(float s) { return (s >= 0.f) ? s : 0.2f * s; }

__device__ __forceinline__ unsigned int encf(float f) {
    unsigned int u = __float_as_uint(f);
    return (u & 0x80000000u) ? ~u : (u | 0x80000000u);
}
__device__ __forceinline__ float decf(unsigned int u) {
    return (u & 0x80000000u) ? __uint_as_float(u & 0x7FFFFFFFu) : __uint_as_float(~u);
}

// ---------------- merged prep kernel ----------------
__global__ __launch_bounds__(256) void prep_kernel(const float* __restrict__ ea,
                                                   const float* __restrict__ Ew,
                                                   const int* __restrict__ adj,
                                                   const float* __restrict__ W,
                                                   const unsigned int* __restrict__ maskw) {
    int blk = blockIdx.x;
    int t = threadIdx.x;
    if (blk < 64) {
        int idx = blk * 256 + t;  // i*128 + j
        float e0 = ea[idx * 2], e1 = ea[idx * 2 + 1];
        bool ok = adj[idx] != 0;
        int i = idx >> 7, j = idx & 127;
        int tidx = j * Vn + i;
        float v0 = ok ? (e0 * Ew[0] + e1 * Ew[1]) : NEGBIG;
        float v1 = ok ? (e0 * Ew[2] + e1 * Ew[3]) : NEGBIG;
        float v2 = ok ? (e0 * Ew[4] + e1 * Ew[5]) : NEGBIG;
        float v3 = ok ? (e0 * Ew[6] + e1 * Ew[7]) : NEGBIG;
        g_efm[0 * 16384 + tidx] = v0;
        g_efm[1 * 16384 + tidx] = v1;
        g_efm[2 * 16384 + tidx] = v2;
        g_efm[3 * 16384 + tidx] = v3;
        float m[4] = {v0, v1, v2, v3};
#pragma unroll
        for (int h = 0; h < 4; h++) {
            float x = m[h];
            x = fmaxf(x, __shfl_xor_sync(0xffffffffu, x, 1));
            x = fmaxf(x, __shfl_xor_sync(0xffffffffu, x, 2));
            x = fmaxf(x, __shfl_xor_sync(0xffffffffu, x, 4));
            x = fmaxf(x, __shfl_xor_sync(0xffffffffu, x, 8));
            x = fmaxf(x, __shfl_xor_sync(0xffffffffu, x, 16));
            if ((t & 31) == 0) atomicMax(&g_efgmax_u[h], encf(x));
        }
    } else if (blk < 128) {
        int gid = (blk - 64) * 256 + t;
        float4 v = ((const float4*)W)[gid];
        uint32_t h01, l01, h23, l23;
        split2(v.x, v.y, h01, l01);
        split2(v.z, v.w, h23, l23);
        ((uint2*)g_Wh)[gid] = make_uint2(h01, h23);
        ((uint2*)g_Wl)[gid] = make_uint2(l01, l23);
    } else {
        __shared__ int okInt, okFloat;
        if (t == 0) { okInt = 1; okFloat = 1; }
        __syncthreads();
        int badI = 0, badF = 0;
        for (int idx = t; idx < 16384; idx += 256) {
            unsigned int v = maskw[idx];
            if (v > 1u) badI = 1;
            if (v != 0u && v != 0x3f800000u) badF = 1;
        }
        if (badI) okInt = 0;
        if (badF) okFloat = 0;
        __syncthreads();
        if (t == 0) g_mask_mode = okFloat ? 2 : (okInt ? 1 : 0);
    }
}

// ---------------- GEMM1: Wx = x @ W^T + fused s_src/s_dst dots ----------------
#define GSTAGE 61440
#define GEMM_SMEM (2 * GSTAGE)

__global__ __launch_bounds__(512) void gemm_wx_kernel(const float* __restrict__ x,
                                                      const float* __restrict__ a) {
    extern __shared__ char gs[];
    int m0 = blockIdx.x * 128;
    int t = threadIdx.x;
    int w = t >> 5, lane = t & 31;
    int wm = w & 3, wn = w >> 2;  // warp tile 32m x 64n; 64n == one head (= wn)

    int rowoffA = ((lane >> 3) & 1) * 8 + (lane & 7);
    int coloffA = (lane >> 4) * 8;
    int rowoffB = (lane >> 4) * 8 + (lane & 7);
    int coloffB = ((lane >> 3) & 1) * 8;

    const uint4* gwh4 = (const uint4*)g_Wh;
    const uint4* gwl4 = (const uint4*)g_Wl;

    int arow0 = t >> 3, acq0 = t & 7;
    int arow1 = arow0 + 64;
    int brow0 = t >> 1, bhalf = t & 1;

    float4 ax0, ax1;
    uint4 rbh0, rbh1, rbl0, rbl1;

    float acc[2][8][4];
#pragma unroll
    for (int mt = 0; mt < 2; mt++)
#pragma unroll
        for (int nt = 0; nt < 8; nt++)
#pragma unroll
            for (int r = 0; r < 4; r++) acc[mt][nt][r] = 0.f;

#define G_LDG(k0)                                                                     \
    do {                                                                              \
        ax0 = *(const float4*)(x + (size_t)(m0 + arow0) * Dn + (k0) + acq0 * 4);      \
        ax1 = *(const float4*)(x + (size_t)(m0 + arow1) * Dn + (k0) + acq0 * 4);      \
        int bi0 = (brow0 * (Dn / 2) + ((k0) >> 1) + bhalf * 8) >> 2;                  \
        rbh0 = gwh4[bi0]; rbh1 = gwh4[bi0 + 1];                                       \
        rbl0 = gwl4[bi0]; rbl1 = gwl4[bi0 + 1];                                       \
    } while (0)

#define G_STS(s)                                                                      \
    do {                                                                              \
        char* st = gs + (s) * GSTAGE;                                                 \
        uint32_t* ah = (uint32_t*)st;                                                 \
        uint32_t* al = (uint32_t*)(st + 10240);                                       \
        uint4* bh = (uint4*)(st + 20480);                                             \
        uint4* bl = (uint4*)(st + 40960);                                             \
        uint32_t h01, l01, h23, l23;                                                  \
        split2(ax0.x, ax0.y, h01, l01); split2(ax0.z, ax0.w, h23, l23);               \
        ah[arow0 * 20 + acq0 * 2] = h01; ah[arow0 * 20 + acq0 * 2 + 1] = h23;         \
        al[arow0 * 20 + acq0 * 2] = l01; al[arow0 * 20 + acq0 * 2 + 1] = l23;         \
        split2(ax1.x, ax1.y, h01, l01); split2(ax1.z, ax1.w, h23, l23);               \
        ah[arow1 * 20 + acq0 * 2] = h01; ah[arow1 * 20 + acq0 * 2 + 1] = h23;         \
        al[arow1 * 20 + acq0 * 2] = l01; al[arow1 * 20 + acq0 * 2 + 1] = l23;         \
        bh[brow0 * 5 + bhalf * 2] = rbh0; bh[brow0 * 5 + bhalf * 2 + 1] = rbh1;       \
        bl[brow0 * 5 + bhalf * 2] = rbl0; bl[brow0 * 5 + bhalf * 2 + 1] = rbl1;       \
    } while (0)

    G_LDG(0);
    G_STS(0);
    G_LDG(32);
    __syncthreads();

    for (int ki = 0; ki < 8; ki++) {
        char* st = gs + (ki & 1) * GSTAGE;
        uint32_t aAh = sptr(st), aAl = sptr(st + 10240);
        uint32_t aBh = sptr(st + 20480), aBl = sptr(st + 40960);
#pragma unroll
        for (int ks = 0; ks < 32; ks += 16) {
            uint32_t Ah[2][4], Al[2][4];
#pragma unroll
            for (int mt = 0; mt < 2; mt++) {
                uint32_t off = (wm * 32 + mt * 16 + rowoffA) * 80 + (ks + coloffA) * 2;
                ldsm_x4(Ah[mt][0], Ah[mt][1], Ah[mt][2], Ah[mt][3], aAh + off);
                ldsm_x4(Al[mt][0], Al[mt][1], Al[mt][2], Al[mt][3], aAl + off);
            }
#pragma unroll
            for (int nb = 0; nb < 4; nb++) {
                uint32_t off = (wn * 64 + nb * 16 + rowoffB) * 80 + (ks + coloffB) * 2;
                uint32_t bh0, bh1, bh2, bh3, bl0, bl1, bl2, bl3;
                ldsm_x4(bh0, bh1, bh2, bh3, aBh + off);
                ldsm_x4(bl0, bl1, bl2, bl3, aBl + off);
#pragma unroll
                for (int mt = 0; mt < 2; mt++) {
                    mma_bf16(acc[mt][nb * 2], Ah[mt], bh0, bh1);
                    mma_bf16(acc[mt][nb * 2], Al[mt], bh0, bh1);
                    mma_bf16(acc[mt][nb * 2], Ah[mt], bl0, bl1);
                    mma_bf16(acc[mt][nb * 2 + 1], Ah[mt], bh2, bh3);
                    mma_bf16(acc[mt][nb * 2 + 1], Al[mt], bh2, bh3);
                    mma_bf16(acc[mt][nb * 2 + 1], Ah[mt], bl2, bl3);
                }
            }
        }
        __syncthreads();
        if (ki < 7) {
            G_STS((ki + 1) & 1);
            if (ki < 6) G_LDG((ki + 2) * 32);
            __syncthreads();
        }
    }

    // epilogue A: write Wx as single fp16
#pragma unroll
    for (int mt = 0; mt < 2; mt++)
#pragma unroll
        for (int nt = 0; nt < 8; nt++) {
            int row0 = m0 + wm * 32 + mt * 16 + (lane >> 2);
            int col = wn * 64 + nt * 8 + (lane & 3) * 2;
            __half2 v01 = __floats2half2_rn(acc[mt][nt][0], acc[mt][nt][1]);
            __half2 v23 = __floats2half2_rn(acc[mt][nt][2], acc[mt][nt][3]);
            *(uint32_t*)&g_Wxh[(size_t)row0 * Dn + col] = *(uint32_t*)&v01;
            *(uint32_t*)&g_Wxh[(size_t)(row0 + 8) * Dn + col] = *(uint32_t*)&v23;
        }

    // epilogue B: fp32 s_src/s_dst dots (head = wn, local dim dl)
    {
        float rs[2][2] = {{0.f, 0.f}, {0.f, 0.f}};
        float rd[2][2] = {{0.f, 0.f}, {0.f, 0.f}};
#pragma unroll
        for (int nt = 0; nt < 8; nt++) {
            int dl = nt * 8 + (lane & 3) * 2;
            float a0s = __ldg(&a[dl]),      a1s = __ldg(&a[dl + 1]);
            float a0d = __ldg(&a[64 + dl]), a1d = __ldg(&a[64 + dl + 1]);
#pragma unroll
            for (int mt = 0; mt < 2; mt++) {
                rs[mt][0] += acc[mt][nt][0] * a0s + acc[mt][nt][1] * a1s;
                rd[mt][0] += acc[mt][nt][0] * a0d + acc[mt][nt][1] * a1d;
                rs[mt][1] += acc[mt][nt][2] * a0s + acc[mt][nt][3] * a1s;
                rd[mt][1] += acc[mt][nt][2] * a0d + acc[mt][nt][3] * a1d;
            }
        }
#pragma unroll
        for (int mt = 0; mt < 2; mt++)
#pragma unroll
            for (int rh = 0; rh < 2; rh++) {
                float vs = rs[mt][rh], vd = rd[mt][rh];
                vs += __shfl_xor_sync(0xffffffffu, vs, 1);
                vs += __shfl_xor_sync(0xffffffffu, vs, 2);
                vd += __shfl_xor_sync(0xffffffffu, vd, 1);
                vd += __shfl_xor_sync(0xffffffffu, vd, 2);
                if ((lane & 3) == 0) {
                    int m = m0 + wm * 32 + mt * 16 + (lane >> 2) + rh * 8;
                    g_sS[wn * (Bn * Vn) + m] = vs;
                    g_sD[wn * (Bn * Vn) + m] = vd;
                }
            }
    }
}

// ---------------- fused attention per (b, h) ----------------
#define WSTR 72  // fp16 stride -> conflict-free ldmatrix
// SMEM: sWh 18432 | misc floats 385 (1540 B)
#define ATT_SMEM_BYTES 20032

__global__ __launch_bounds__(256, 4) void gat_attn_kernel(const void* __restrict__ maskp,
                                                          float* __restrict__ out) {
    extern __shared__ char smem[];
    __half* sWh = (__half*)smem;
    float* sMb  = (float*)(smem + 18432);  // 128
    float* sSrc = sMb + 128;               // 128
    float* sDst = sMb + 256;               // 128
    float* sMax = sMb + 384;               // 1

    int h = blockIdx.x;
    int b = blockIdx.y;
    int t = threadIdx.x;

    if (t < 128) {
        int mode = g_mask_mode;
        bool mv;
        int idx = b * Vn + t;
        if (mode == 0)      mv = ((const unsigned char*)maskp)[idx] != 0;
        else if (mode == 1) mv = ((const int*)maskp)[idx] != 0;
        else                mv = ((const float*)maskp)[idx] != 0.f;
        float mb = mv ? NEGBIG : 0.f;
        sMb[t] = mb;
        sSrc[t] = g_sS[h * (Bn * Vn) + b * Vn + t] + mb;
        sDst[t] = g_sD[h * (Bn * Vn) + b * Vn + t] + mb;
    }

    // ---- pure copy: Wx[b,:,h,:] fp16 -> SMEM [i][d] (4x STS.128 each) ----
    {
        int i = t >> 1, half = t & 1;
        size_t base32 = (((size_t)(b * Vn + i) * Dn + h * DHn) >> 1) + half * 16;
        const uint4* ph4 = (const uint4*)((const uint32_t*)g_Wxh + base32);
        uint4* wh4 = (uint4*)sWh;
        int di = i * 9 + half * 4;  // 9 uint4 per row (72 fp16)
#pragma unroll
        for (int k = 0; k < 4; k++) wh4[di + k] = ph4[k];
    }
    __syncthreads();
    if (t < 32) {
        float m = fmaxf(fmaxf(sSrc[t], sSrc[t + 32]), fmaxf(sSrc[t + 64], sSrc[t + 96]));
        m = fmaxf(m, __shfl_xor_sync(0xffffffffu, m, 1));
        m = fmaxf(m, __shfl_xor_sync(0xffffffffu, m, 2));
        m = fmaxf(m, __shfl_xor_sync(0xffffffffu, m, 4));
        m = fmaxf(m, __shfl_xor_sync(0xffffffffu, m, 8));
        m = fmaxf(m, __shfl_xor_sync(0xffffffffu, m, 16));
        if (t == 0) sMax[0] = m;
    }
    __syncthreads();

    // ---- single pass: scores -> p = exp(e - m_ub) fp16 -> f16 mma ----
    int w = t >> 5, lane = t & 31;
    int q = lane >> 2, cpos = (lane & 3) * 2;
    int j0 = w * 16 + q;
    int j1 = j0 + 8;

    float dst0 = sDst[j0], dst1 = sDst[j1];
    float m0v = lrelu(sMax[0] + dst0 + decf(g_efgmax_u[h]));
    float m1v = lrelu(sMax[0] + dst1 + decf(g_efgmax_u[h]));

    const float* ef0 = g_efm + h * (Vn * Vn) + j0 * Vn;
    const float* ef1 = g_efm + h * (Vn * Vn) + j1 * Vn;

    int rowoffBt = ((lane >> 3) & 1) * 8 + (lane & 7);
    int coloffBt = (lane >> 4) * 8;
    uint32_t aWh = sptr(sWh);

    float acc[8][4];
#pragma unroll
    for (int nt = 0; nt < 8; nt++)
#pragma unroll
        for (int r = 0; r < 4; r++) acc[nt][r] = 0.f;

    float s0 = 0.f, s1 = 0.f;
#pragma unroll
    for (int k0 = 0; k0 < 8; k0++) {
        int ib = k0 * 16 + cpos;
        float2 sA = *(const float2*)&sSrc[ib];
        float2 sB = *(const float2*)&sSrc[ib + 8];
        float2 eA0 = *(const float2*)&ef0[ib];
        float2 eB0 = *(const float2*)&ef0[ib + 8];
        float2 eA1 = *(const float2*)&ef1[ib];
        float2 eB1 = *(const float2*)&ef1[ib + 8];
        float p00 = __expf(lrelu(sA.x + dst0 + eA0.x) - m0v);
        float p01 = __expf(lrelu(sA.y + dst0 + eA0.y) - m0v);
        float p02 = __expf(lrelu(sB.x + dst0 + eB0.x) - m0v);
        float p03 = __expf(lrelu(sB.y + dst0 + eB0.y) - m0v);
        float p10 = __expf(lrelu(sA.x + dst1 + eA1.x) - m1v);
        float p11 = __expf(lrelu(sA.y + dst1 + eA1.y) - m1v);
        float p12 = __expf(lrelu(sB.x + dst1 + eB1.x) - m1v);
        float p13 = __expf(lrelu(sB.y + dst1 + eB1.y) - m1v);
        s0 += p00 + p01 + p02 + p03;
        s1 += p10 + p11 + p12 + p13;
        uint32_t A[4];
        {
            __half2 t0 = __floats2half2_rn(p00, p01);
            __half2 t1 = __floats2half2_rn(p10, p11);
            __half2 t2 = __floats2half2_rn(p02, p03);
            __half2 t3 = __floats2half2_rn(p12, p13);
            A[0] = *(uint32_t*)&t0;
            A[1] = *(uint32_t*)&t1;
            A[2] = *(uint32_t*)&t2;
            A[3] = *(uint32_t*)&t3;
        }
#pragma unroll
        for (int nc = 0; nc < 4; nc++) {
            uint32_t offB = ((k0 * 16 + rowoffBt) * WSTR + nc * 16 + coloffBt) * 2;
            uint32_t bh0, bh1, bh2, bh3;
            ldsm_x4_t(bh0, bh1, bh2, bh3, aWh + offB);
            mma_f16(acc[nc * 2], A, bh0, bh1);
            mma_f16(acc[nc * 2 + 1], A, bh2, bh3);
        }
    }
    s0 += __shfl_xor_sync(0xffffffffu, s0, 1);
    s0 += __shfl_xor_sync(0xffffffffu, s0, 2);
    s1 += __shfl_xor_sync(0xffffffffu, s1, 1);
    s1 += __shfl_xor_sync(0xffffffffu, s1, 2);
    float inv0 = 1.0f / s0;
    float inv1 = 1.0f / s1;

    bool msk0 = (sMb[j0] != 0.f);
    bool msk1 = (sMb[j1] != 0.f);
    float* out0 = out + (size_t)(b * Vn + j0) * Dn + h * DHn + cpos;
    float* out1 = out + (size_t)(b * Vn + j1) * Dn + h * DHn + cpos;
#pragma unroll
    for (int nt = 0; nt < 8; nt++) {
        {
            float v0 = acc[nt][0] * inv0;
            float v1 = acc[nt][1] * inv0;
            float2 o;
            o.x = msk0 ? 0.f : (v0 > 0.f ? v0 : __expf(v0) - 1.f);
            o.y = msk0 ? 0.f : (v1 > 0.f ? v1 : __expf(v1) - 1.f);
            *(float2*)(out0 + nt * 8) = o;
        }
        {
            float v0 = acc[nt][2] * inv1;
            float v1 = acc[nt][3] * inv1;
            float2 o;
            o.x = msk1 ? 0.f : (v0 > 0.f ? v0 : __expf(v0) - 1.f);
            o.y = msk1 ? 0.f : (v1 > 0.f ? v1 : __expf(v1) - 1.f);
            *(float2*)(out1 + nt * 8) = o;
        }
    }
}

// ---------------- launch ----------------
extern "C" void kernel_launch(void* const* d_in, const int* in_sizes, int n_in,
                              void* d_out, int out_size) {
    const float* x    = (const float*)d_in[0];
    const int*   adj  = (const int*)d_in[1];
    const float* ea   = (const float*)d_in[2];
    const void*  mask = (const void*)d_in[3];
    const float* W    = (const float*)d_in[4];
    const float* a    = (const float*)d_in[5];
    const float* Ew   = (const float*)d_in[6];
    float* out = (float*)d_out;

    cudaFuncSetAttribute(gat_attn_kernel, cudaFuncAttributeMaxDynamicSharedMemorySize,
                         ATT_SMEM_BYTES);
    cudaFuncSetAttribute(gemm_wx_kernel, cudaFuncAttributeMaxDynamicSharedMemorySize,
                         GEMM_SMEM);

    prep_kernel<<<129, 256>>>(ea, Ew, adj, W, (const unsigned int*)mask);
    gemm_wx_kernel<<<(Bn * Vn) / 128, 512, GEMM_SMEM>>>(x, a);
    gat_attn_kernel<<<dim3(Hn, Bn), 256, ATT_SMEM_BYTES>>>(mask, out);
}